// round 8
// baseline (speedup 1.0000x reference)
#include <cuda_runtime.h>
#include <cuda_bf16.h>
#include <cstdint>
#include <cstddef>

#define T_SEQ 512
#define BATCH 64
#define NTOK  (BATCH * T_SEQ)   // 32768

typedef unsigned long long ull;

// ---- packed f32x2 helpers (sm_103a FFMA2 path) -----------------------------
__device__ __forceinline__ void fma2(ull& d, ull a, ull b) {
    asm("fma.rn.f32x2 %0, %1, %2, %0;" : "+l"(d) : "l"(a), "l"(b));
}
__device__ __forceinline__ ull pk2(float lo, float hi) {
    ull d; asm("mov.b64 %0, {%1, %2};" : "=l"(d) : "f"(lo), "f"(hi)); return d;
}
__device__ __forceinline__ float2 upk2(ull v) {
    float2 r; asm("mov.b64 {%0, %1}, %2;" : "=f"(r.x), "=f"(r.y) : "l"(v)); return r;
}

// ----------------------------- scratch ------------------------------------
__device__ float g_xw[(size_t)NTOK * 960];
__device__ float g_h1[(size_t)NTOK * 320];
__device__ float g_seq[(size_t)NTOK * 320];
__device__ float g_keys[(size_t)NTOK * 160];
__device__ float g_logits[(size_t)NTOK * 4];
__device__ float g_motion[NTOK];
__device__ float g_pooled[BATCH * 320];

// ----------------------- SGEMM: C = A(MxK) * B(NxK)^T + bias ---------------
// (exact R6 version: proven 539us/launch)
#define BM 128
#define BN 128
#define BK 16

__global__ void __launch_bounds__(256) sgemm_bias(
    const float* __restrict__ A, const float* __restrict__ B,
    const float* __restrict__ bias, float* __restrict__ C,
    int M, int N, int K, int act)
{
    __shared__ __align__(16) float As[BK][BM + 4];
    __shared__ __align__(16) float Bs[BK][BN + 4];

    const int tid = threadIdx.x;
    const int tx = tid & 15;
    const int ty = tid >> 4;
    const int bm = blockIdx.y * BM;
    const int bn = blockIdx.x * BN;

    ull acc2[8][4];
#pragma unroll
    for (int i = 0; i < 8; i++)
#pragma unroll
        for (int j = 0; j < 4; j++) acc2[i][j] = 0ull;

    const int ntiles = K / BK;
    for (int kt = 0; kt < ntiles; kt++) {
        const int k0 = kt * BK;
#pragma unroll
        for (int i = 0; i < 2; i++) {
            int f = tid * 2 + i;
            int r = f >> 2, c = f & 3;
            float4 v = *reinterpret_cast<const float4*>(A + (size_t)(bm + r) * K + k0 + c * 4);
            As[c * 4 + 0][r] = v.x; As[c * 4 + 1][r] = v.y;
            As[c * 4 + 2][r] = v.z; As[c * 4 + 3][r] = v.w;
        }
#pragma unroll
        for (int i = 0; i < 2; i++) {
            int f = tid * 2 + i;
            int r = f >> 2, c = f & 3;
            float4 v = make_float4(0.f, 0.f, 0.f, 0.f);
            if (bn + r < N)
                v = *reinterpret_cast<const float4*>(B + (size_t)(bn + r) * K + k0 + c * 4);
            Bs[c * 4 + 0][r] = v.x; Bs[c * 4 + 1][r] = v.y;
            Bs[c * 4 + 2][r] = v.z; Bs[c * 4 + 3][r] = v.w;
        }
        __syncthreads();
#pragma unroll
        for (int kk = 0; kk < BK; kk++) {
            float4 a0 = *reinterpret_cast<const float4*>(&As[kk][ty * 8]);
            float4 a1 = *reinterpret_cast<const float4*>(&As[kk][ty * 8 + 4]);
            ulonglong2 B0 = *reinterpret_cast<const ulonglong2*>(&Bs[kk][tx * 8]);
            ulonglong2 B1 = *reinterpret_cast<const ulonglong2*>(&Bs[kk][tx * 8 + 4]);
            float av[8] = {a0.x, a0.y, a0.z, a0.w, a1.x, a1.y, a1.z, a1.w};
#pragma unroll
            for (int i = 0; i < 8; i++) {
                ull ap = pk2(av[i], av[i]);
                fma2(acc2[i][0], ap, B0.x);
                fma2(acc2[i][1], ap, B0.y);
                fma2(acc2[i][2], ap, B1.x);
                fma2(acc2[i][3], ap, B1.y);
            }
        }
        __syncthreads();
    }
#pragma unroll
    for (int i = 0; i < 8; i++) {
        size_t row = (size_t)(bm + ty * 8 + i);
#pragma unroll
        for (int jp = 0; jp < 4; jp++) {
            float2 cc = upk2(acc2[i][jp]);
            int col = bn + tx * 8 + jp * 2;
            if (col < N) {
                float v = cc.x + bias[col];
                if (act) v = tanhf(v);
                C[row * N + col] = v;
            }
            if (col + 1 < N) {
                float v = cc.y + bias[col + 1];
                if (act) v = tanhf(v);
                C[row * N + col + 1] = v;
            }
        }
    }
}

// --------------------------- GRU layer (2-CTA cluster, NB=1) ----------------
// 256 CTAs = 128 clusters. cluster c = blockIdx.x>>1: dir = c&1, batch = c>>1.
// rank = blockIdx.x&1 owns hidden units [rank*80, rank*80+80).
// ~110 regs/thread -> 2 CTAs co-resident per SM: the per-step cluster-barrier
// wait of one CTA is hidden by the other CTA's issue.
__global__ void __cluster_dims__(2, 1, 1) __launch_bounds__(256, 2) gru_layer(
    const float* __restrict__ xw,    // (NTOK, 960): col = dir*480 + gate*160 + unit
    const float* __restrict__ whh,   // (2, 480, 160)
    const float* __restrict__ bhh,   // (2, 480)
    float* __restrict__ out)         // (NTOK, 320): col = dir*160 + unit
{
    __shared__ __align__(16) float h_s[2][160];
    __shared__ float a_s[4][80];   // a_r, a_z, hn, xn

    const int tid  = threadIdx.x;
    const int rank = blockIdx.x & 1;
    const int c    = blockIdx.x >> 1;
    const int dir  = c & 1;
    const int bat  = c >> 1;
    const int peer = rank ^ 1;

    const int gate = tid / 80;      // valid for tid < 240
    const int j    = tid % 80;
    const int grow = dir * 480 + gate * 160 + rank * 80 + j;

    // one-time preload of this thread's Whh row into PACKED registers
    ull wp[80];
    float bb = 0.f;
    if (tid < 240) {
        const float4* wq = reinterpret_cast<const float4*>(whh + (size_t)grow * 160);
#pragma unroll
        for (int kb = 0; kb < 40; kb++) {
            float4 v = wq[kb];
            wp[2 * kb]     = pk2(v.x, v.y);
            wp[2 * kb + 1] = pk2(v.z, v.w);
        }
        bb = bhh[grow];
    }

    for (int f = tid; f < 2 * 160; f += blockDim.x)
        (&h_s[0][0])[f] = 0.f;
    __syncthreads();
    asm volatile("barrier.cluster.arrive.aligned;" ::: "memory");
    asm volatile("barrier.cluster.wait.aligned;" ::: "memory");

    const int xcol = dir * 480 + gate * 160 + rank * 80 + j;
    const size_t tokbase = (size_t)bat * T_SEQ;

    // preload xW for step 0
    float xv = 0.f;
    if (tid < 240)
        xv = xw[(tokbase + (dir ? (T_SEQ - 1) : 0)) * 960 + xcol];

    int cur = 0;
    for (int s = 0; s < T_SEQ; s++) {
        const int t = dir ? (T_SEQ - 1 - s) : s;

        if (tid < 240) {
            ull ca = 0ull, cb = 0ull;
            const ull* hq = reinterpret_cast<const ull*>(&h_s[cur][0]);
#pragma unroll
            for (int kb = 0; kb < 20; kb++) {
                ulonglong2 H = *reinterpret_cast<const ulonglong2*>(hq + 4 * kb);
                ulonglong2 H2 = *reinterpret_cast<const ulonglong2*>(hq + 4 * kb + 2);
                fma2(ca, wp[4 * kb],     H.x);
                fma2(cb, wp[4 * kb + 1], H.y);
                fma2(ca, wp[4 * kb + 2], H2.x);
                fma2(cb, wp[4 * kb + 3], H2.y);
            }
            float2 p = upk2(ca), q = upk2(cb);
            float accum = bb + ((p.x + p.y) + (q.x + q.y));

            if (gate == 0)      a_s[0][j] = xv + accum;
            else if (gate == 1) a_s[1][j] = xv + accum;
            else {              a_s[2][j] = accum;
                                a_s[3][j] = xv; }
        }
        __syncthreads();

        if (tid < 80) {
            int jj = tid;
            float ar = a_s[0][jj];
            float az = a_s[1][jj];
            float hn = a_s[2][jj];
            float xn = a_s[3][jj];
            float r = 1.f / (1.f + expf(-ar));
            float z = 1.f / (1.f + expf(-az));
            float n = tanhf(xn + r * hn);
            float hp = h_s[cur][rank * 80 + jj];
            float hnew = (1.f - z) * n + z * hp;
            int nxt = cur ^ 1;
            float* lp = &h_s[nxt][rank * 80 + jj];
            *lp = hnew;                                   // local half
            uint32_t saddr = (uint32_t)__cvta_generic_to_shared(lp);
            uint32_t paddr;
            asm volatile("mapa.shared::cluster.u32 %0, %1, %2;"
                         : "=r"(paddr) : "r"(saddr), "r"(peer));
            asm volatile("st.shared::cluster.f32 [%0], %1;"
                         :: "r"(paddr), "f"(hnew) : "memory");
            out[(tokbase + t) * 320 + dir * 160 + rank * 80 + jj] = hnew;
        }
        asm volatile("barrier.cluster.arrive.aligned;" ::: "memory");

        // hide next step's xW gather behind the cluster barrier
        if (s + 1 < T_SEQ && tid < 240) {
            const int tn = dir ? (T_SEQ - 2 - s) : (s + 1);
            xv = xw[(tokbase + tn) * 960 + xcol];
        }
        asm volatile("barrier.cluster.wait.aligned;" ::: "memory");
        cur ^= 1;
    }
}

// ------------------------------ attention bits -----------------------------
__global__ void __launch_bounds__(256) logits_kernel(
    const float* __restrict__ keys, const float* __restrict__ sw,
    const float* __restrict__ sb, float* __restrict__ logits)
{
    int warp = (blockIdx.x * blockDim.x + threadIdx.x) >> 5;
    int lane = threadIdx.x & 31;
    if (warp >= NTOK) return;
    const float* kr = keys + (size_t)warp * 160;
    float a0 = 0.f, a1 = 0.f, a2 = 0.f, a3 = 0.f;
    for (int k = lane; k < 160; k += 32) {
        float kv = kr[k];
        a0 = fmaf(kv, sw[0 * 160 + k], a0);
        a1 = fmaf(kv, sw[1 * 160 + k], a1);
        a2 = fmaf(kv, sw[2 * 160 + k], a2);
        a3 = fmaf(kv, sw[3 * 160 + k], a3);
    }
#pragma unroll
    for (int off = 16; off; off >>= 1) {
        a0 += __shfl_xor_sync(0xffffffffu, a0, off);
        a1 += __shfl_xor_sync(0xffffffffu, a1, off);
        a2 += __shfl_xor_sync(0xffffffffu, a2, off);
        a3 += __shfl_xor_sync(0xffffffffu, a3, off);
    }
    if (lane == 0) {
        float* o = logits + (size_t)warp * 4;
        o[0] = a0 + sb[0]; o[1] = a1 + sb[1]; o[2] = a2 + sb[2]; o[3] = a3 + sb[3];
    }
}

__global__ void __launch_bounds__(512) motion_kernel(
    const float* __restrict__ x, float* __restrict__ motion)
{
    __shared__ float sd[512];
    __shared__ float red[512];
    int b = blockIdx.x, t = threadIdx.x;
    float d = 0.f;
    if (t >= 1) {
        const float4* r1 = reinterpret_cast<const float4*>(x + ((size_t)b * 512 + t) * 128);
        const float4* r0 = reinterpret_cast<const float4*>(x + ((size_t)b * 512 + t - 1) * 128);
        float acc = 0.f;
#pragma unroll 8
        for (int q = 0; q < 32; q++) {
            float4 a = r1[q], c = r0[q];
            float dx = a.x - c.x, dy = a.y - c.y, dz = a.z - c.z, dw = a.w - c.w;
            acc += dx * dx + dy * dy + dz * dz + dw * dw;
        }
        d = sqrtf(acc);
    }
    sd[t] = d;
    __syncthreads();
    if (t == 0) sd[0] = sd[1];
    __syncthreads();
    d = sd[t];
    red[t] = d; __syncthreads();
    for (int off = 256; off; off >>= 1) { if (t < off) red[t] += red[t + off]; __syncthreads(); }
    float mean = red[0] / 512.f;
    __syncthreads();
    float dd = d - mean;
    red[t] = dd * dd; __syncthreads();
    for (int off = 256; off; off >>= 1) { if (t < off) red[t] += red[t + off]; __syncthreads(); }
    float stdv = sqrtf(red[0] / 511.f);
    motion[(size_t)b * 512 + t] = (d - mean) / (stdv + 1e-6f);
}

__global__ void __launch_bounds__(512) softmax_kernel(
    const float* __restrict__ logits, const float* __restrict__ motion,
    float* __restrict__ wmean_out)
{
    __shared__ float4 red[512];
    int b = blockIdx.x, t = threadIdx.x;
    size_t tok = (size_t)b * 512 + t;
    float4 l = *reinterpret_cast<const float4*>(logits + tok * 4);
    float m = motion[tok];
    l.x += m; l.y += m; l.z += m; l.w += m;
    red[t] = l; __syncthreads();
    for (int off = 256; off; off >>= 1) {
        if (t < off) {
            float4 a = red[t], c = red[t + off];
            a.x = fmaxf(a.x, c.x); a.y = fmaxf(a.y, c.y);
            a.z = fmaxf(a.z, c.z); a.w = fmaxf(a.w, c.w);
            red[t] = a;
        }
        __syncthreads();
    }
    float4 mx = red[0];
    __syncthreads();
    float4 e;
    e.x = expf(l.x - mx.x); e.y = expf(l.y - mx.y);
    e.z = expf(l.z - mx.z); e.w = expf(l.w - mx.w);
    red[t] = e; __syncthreads();
    for (int off = 256; off; off >>= 1) {
        if (t < off) {
            float4 a = red[t], c = red[t + off];
            a.x += c.x; a.y += c.y; a.z += c.z; a.w += c.w;
            red[t] = a;
        }
        __syncthreads();
    }
    float4 s = red[0];
    wmean_out[tok] = 0.25f * (e.x / s.x + e.y / s.y + e.z / s.z + e.w / s.w);
}

__global__ void __launch_bounds__(320) pool_kernel(
    const float* __restrict__ seq, const float* __restrict__ wm,
    float* __restrict__ pooled)
{
    __shared__ float sw[512];
    int b = blockIdx.x, d = threadIdx.x;
    for (int i = d; i < 512; i += 320) sw[i] = wm[(size_t)b * 512 + i];
    __syncthreads();
    float acc = 0.f;
    const float* sp = seq + (size_t)b * 512 * 320 + d;
    for (int t = 0; t < 512; t++) acc = fmaf(sp[(size_t)t * 320], sw[t], acc);
    pooled[b * 320 + d] = acc;
}

__global__ void __launch_bounds__(256) final_kernel(
    const float* __restrict__ pooled, const float* __restrict__ pw,
    const float* __restrict__ pb, const float* __restrict__ lng,
    const float* __restrict__ lnb, float* __restrict__ out)
{
    __shared__ float sp[320];
    __shared__ float red[256];
    int b = blockIdx.x, e = threadIdx.x;
    for (int i = e; i < 320; i += 256) sp[i] = pooled[b * 320 + i];
    __syncthreads();
    float acc = 0.f;
    const float* wr = pw + (size_t)e * 320;
#pragma unroll 4
    for (int k = 0; k < 320; k += 4) {
        acc = fmaf(wr[k + 0], sp[k + 0], acc);
        acc = fmaf(wr[k + 1], sp[k + 1], acc);
        acc = fmaf(wr[k + 2], sp[k + 2], acc);
        acc = fmaf(wr[k + 3], sp[k + 3], acc);
    }
    acc += pb[e];
    red[e] = acc; __syncthreads();
    for (int off = 128; off; off >>= 1) { if (e < off) red[e] += red[e + off]; __syncthreads(); }
    float mean = red[0] / 256.f;
    __syncthreads();
    float dd = acc - mean;
    red[e] = dd * dd; __syncthreads();
    for (int off = 128; off; off >>= 1) { if (e < off) red[e] += red[e + off]; __syncthreads(); }
    float var = red[0] / 256.f;
    __syncthreads();
    float v = dd * rsqrtf(var + 1e-5f) * lng[e] + lnb[e];
    red[e] = v * v; __syncthreads();
    for (int off = 128; off; off >>= 1) { if (e < off) red[e] += red[e + off]; __syncthreads(); }
    float nrm = fmaxf(sqrtf(red[0]), 1e-12f);
    out[b * 256 + e] = v / nrm;
}

// ------------------------------- launch -------------------------------------
extern "C" void kernel_launch(void* const* d_in, const int* in_sizes, int n_in,
                              void* d_out, int out_size)
{
    const float* x       = (const float*)d_in[0];
    const float* Wih0    = (const float*)d_in[1];
    const float* Whh0    = (const float*)d_in[2];
    const float* bih0    = (const float*)d_in[3];
    const float* bhh0    = (const float*)d_in[4];
    const float* Wih1    = (const float*)d_in[5];
    const float* Whh1    = (const float*)d_in[6];
    const float* bih1    = (const float*)d_in[7];
    const float* bhh1    = (const float*)d_in[8];
    const float* key_w   = (const float*)d_in[9];
    const float* key_b   = (const float*)d_in[10];
    const float* score_w = (const float*)d_in[11];
    const float* score_b = (const float*)d_in[12];
    const float* proj_w  = (const float*)d_in[13];
    const float* proj_b  = (const float*)d_in[14];
    const float* ln_g    = (const float*)d_in[15];
    const float* ln_b    = (const float*)d_in[16];
    float* out = (float*)d_out;
    float* out_emb = out;            // (64, 256)
    float* out_wm  = out + 64 * 256; // (64, 512)

    float *xw, *h1, *seq, *keys, *logits, *motion, *pooled;
    cudaGetSymbolAddress((void**)&xw,     g_xw);
    cudaGetSymbolAddress((void**)&h1,     g_h1);
    cudaGetSymbolAddress((void**)&seq,    g_seq);
    cudaGetSymbolAddress((void**)&keys,   g_keys);
    cudaGetSymbolAddress((void**)&logits, g_logits);
    cudaGetSymbolAddress((void**)&motion, g_motion);
    cudaGetSymbolAddress((void**)&pooled, g_pooled);

    // motion is independent of the GRU chain
    motion_kernel<<<BATCH, 512>>>(x, motion);

    // layer 0
    sgemm_bias<<<dim3((960 + BN - 1) / BN, NTOK / BM), 256>>>(x, Wih0, bih0, xw, NTOK, 960, 128, 0);
    gru_layer<<<256, 256>>>(xw, Whh0, bhh0, h1);

    // layer 1
    sgemm_bias<<<dim3((960 + BN - 1) / BN, NTOK / BM), 256>>>(h1, Wih1, bih1, xw, NTOK, 960, 320, 0);
    gru_layer<<<256, 256>>>(xw, Whh1, bhh1, seq);

    // keys = tanh(seq @ key_w^T + key_b)
    sgemm_bias<<<dim3((160 + BN - 1) / BN, NTOK / BM), 256>>>(seq, key_w, key_b, keys, NTOK, 160, 320, 1);

    // attention logits, softmax over T (writes weights.mean to out_wm)
    logits_kernel<<<NTOK / 8, 256>>>(keys, score_w, score_b, logits);
    softmax_kernel<<<BATCH, 512>>>(logits, motion, out_wm);

    // pooled + projection + LN + L2 norm
    pool_kernel<<<BATCH, 320>>>(seq, out_wm, pooled);
    final_kernel<<<BATCH, 256>>>(pooled, proj_w, proj_b, ln_g, ln_b, out_emb);
}

// round 9
// speedup vs baseline: 1.7632x; 1.7632x over previous
#include <cuda_runtime.h>
#include <cuda_bf16.h>
#include <cstdint>
#include <cstddef>

#define T_SEQ 512
#define BATCH 64
#define NTOK  (BATCH * T_SEQ)   // 32768
#define NB 2                    // batches per GRU cluster
#define QH 40                   // hidden units / k-range per CTA (160/4)

typedef unsigned long long ull;

// ---- packed f32x2 helpers (sm_103a FFMA2 path) -----------------------------
__device__ __forceinline__ void fma2(ull& d, ull a, ull b) {
    asm("fma.rn.f32x2 %0, %1, %2, %0;" : "+l"(d) : "l"(a), "l"(b));
}
__device__ __forceinline__ ull pk2(float lo, float hi) {
    ull d; asm("mov.b64 %0, {%1, %2};" : "=l"(d) : "f"(lo), "f"(hi)); return d;
}
__device__ __forceinline__ float2 upk2(ull v) {
    float2 r; asm("mov.b64 {%0, %1}, %2;" : "=f"(r.x), "=f"(r.y) : "l"(v)); return r;
}
__device__ __forceinline__ float hsum2(ull v) {
    float2 e = upk2(v); return e.x + e.y;
}

// ----------------------------- scratch ------------------------------------
__device__ float g_xw[(size_t)NTOK * 960];
__device__ float g_h1[(size_t)NTOK * 320];
__device__ float g_seq[(size_t)NTOK * 320];
__device__ float g_keys[(size_t)NTOK * 160];
__device__ float g_logits[(size_t)NTOK * 4];
__device__ float g_motion[NTOK];
__device__ float g_pooled[BATCH * 320];

// ----------------------- SGEMM: C = A(MxK) * B(NxK)^T + bias ---------------
// (exact R6 version: proven 539us/launch)
#define BM 128
#define BN 128
#define BK 16

__global__ void __launch_bounds__(256) sgemm_bias(
    const float* __restrict__ A, const float* __restrict__ B,
    const float* __restrict__ bias, float* __restrict__ C,
    int M, int N, int K, int act)
{
    __shared__ __align__(16) float As[BK][BM + 4];
    __shared__ __align__(16) float Bs[BK][BN + 4];

    const int tid = threadIdx.x;
    const int tx = tid & 15;
    const int ty = tid >> 4;
    const int bm = blockIdx.y * BM;
    const int bn = blockIdx.x * BN;

    ull acc2[8][4];
#pragma unroll
    for (int i = 0; i < 8; i++)
#pragma unroll
        for (int j = 0; j < 4; j++) acc2[i][j] = 0ull;

    const int ntiles = K / BK;
    for (int kt = 0; kt < ntiles; kt++) {
        const int k0 = kt * BK;
#pragma unroll
        for (int i = 0; i < 2; i++) {
            int f = tid * 2 + i;
            int r = f >> 2, c = f & 3;
            float4 v = *reinterpret_cast<const float4*>(A + (size_t)(bm + r) * K + k0 + c * 4);
            As[c * 4 + 0][r] = v.x; As[c * 4 + 1][r] = v.y;
            As[c * 4 + 2][r] = v.z; As[c * 4 + 3][r] = v.w;
        }
#pragma unroll
        for (int i = 0; i < 2; i++) {
            int f = tid * 2 + i;
            int r = f >> 2, c = f & 3;
            float4 v = make_float4(0.f, 0.f, 0.f, 0.f);
            if (bn + r < N)
                v = *reinterpret_cast<const float4*>(B + (size_t)(bn + r) * K + k0 + c * 4);
            Bs[c * 4 + 0][r] = v.x; Bs[c * 4 + 1][r] = v.y;
            Bs[c * 4 + 2][r] = v.z; Bs[c * 4 + 3][r] = v.w;
        }
        __syncthreads();
#pragma unroll
        for (int kk = 0; kk < BK; kk++) {
            float4 a0 = *reinterpret_cast<const float4*>(&As[kk][ty * 8]);
            float4 a1 = *reinterpret_cast<const float4*>(&As[kk][ty * 8 + 4]);
            ulonglong2 B0 = *reinterpret_cast<const ulonglong2*>(&Bs[kk][tx * 8]);
            ulonglong2 B1 = *reinterpret_cast<const ulonglong2*>(&Bs[kk][tx * 8 + 4]);
            float av[8] = {a0.x, a0.y, a0.z, a0.w, a1.x, a1.y, a1.z, a1.w};
#pragma unroll
            for (int i = 0; i < 8; i++) {
                ull ap = pk2(av[i], av[i]);
                fma2(acc2[i][0], ap, B0.x);
                fma2(acc2[i][1], ap, B0.y);
                fma2(acc2[i][2], ap, B1.x);
                fma2(acc2[i][3], ap, B1.y);
            }
        }
        __syncthreads();
    }
#pragma unroll
    for (int i = 0; i < 8; i++) {
        size_t row = (size_t)(bm + ty * 8 + i);
#pragma unroll
        for (int jp = 0; jp < 4; jp++) {
            float2 cc = upk2(acc2[i][jp]);
            int col = bn + tx * 8 + jp * 2;
            if (col < N) {
                float v = cc.x + bias[col];
                if (act) v = tanhf(v);
                C[row * N + col] = v;
            }
            if (col + 1 < N) {
                float v = cc.y + bias[col + 1];
                if (act) v = tanhf(v);
                C[row * N + col + 1] = v;
            }
        }
    }
}

// --------------------------- GRU layer (4-CTA cluster, K-split) -------------
// 256 CTAs = 64 clusters of 4. cluster c = blockIdx.x>>2: dir = c&1,
// batch group = c>>1 (NB batches). rank = blockIdx.x&3 owns k-quarter AND
// hidden units [rank*40, rank*40+40). Each thread holds 2 rows x 40 k of Whh
// in registers (80 regs) -> fits under the 128-reg cap -> 2 CTAs/SM
// co-resident, mutually hiding the per-step cluster-barrier wait.
// Partial dot-products are shipped to the unit-owner CTA via
// st.shared::cluster (double-buffered by step parity); h stays CTA-local.
__global__ void __cluster_dims__(4, 1, 1) __launch_bounds__(256, 2) gru_layer(
    const float* __restrict__ xw,    // (NTOK, 960): col = dir*480 + gate*160 + unit
    const float* __restrict__ whh,   // (2, 480, 160)
    const float* __restrict__ bhh,   // (2, 480)
    float* __restrict__ out)         // (NTOK, 320): col = dir*160 + unit
{
    __shared__ __align__(16) float h_s[2][NB][QH];          // own units only
    __shared__ __align__(16) float a_part[2][4][3][QH][NB]; // [buf][sender][gate][u][b]

    const int tid  = threadIdx.x;
    const int rank = blockIdx.x & 3;
    const int c    = blockIdx.x >> 2;
    const int dir  = c & 1;
    const int b0   = (c >> 1) * NB;

    const int g  = (tid < 240) ? (tid / 80) : 0;
    const int j  = tid % 80;
    const int ul = j % 40;                 // local unit slot at destination
    const int r0 = j / 40;                 // dest rank of row0 (unit j)
    const int r1 = 2 + j / 40;             // dest rank of row1 (unit j+80)

    // ---- one-time: load 2 rows x 40 k of Whh into packed registers --------
    ull wp0[20], wp1[20];
    if (tid < 240) {
        const int grow0 = dir * 480 + g * 160 + j;
        const int grow1 = dir * 480 + g * 160 + j + 80;
        const float4* w0 = reinterpret_cast<const float4*>(whh + (size_t)grow0 * 160 + rank * QH);
        const float4* w1 = reinterpret_cast<const float4*>(whh + (size_t)grow1 * 160 + rank * QH);
#pragma unroll
        for (int q = 0; q < 10; q++) {
            float4 a = w0[q]; wp0[2 * q] = pk2(a.x, a.y); wp0[2 * q + 1] = pk2(a.z, a.w);
            float4 b = w1[q]; wp1[2 * q] = pk2(b.x, b.y); wp1[2 * q + 1] = pk2(b.z, b.w);
        }
    }

    // precompute mapa'd destination addresses (both parity buffers, both rows)
    uint32_t dst0[2], dst1[2];
    if (tid < 240) {
#pragma unroll
        for (int buf = 0; buf < 2; buf++) {
            uint32_t base = (uint32_t)__cvta_generic_to_shared(&a_part[buf][rank][g][ul][0]);
            asm volatile("mapa.shared::cluster.u32 %0, %1, %2;" : "=r"(dst0[buf]) : "r"(base), "r"(r0));
            asm volatile("mapa.shared::cluster.u32 %0, %1, %2;" : "=r"(dst1[buf]) : "r"(base), "r"(r1));
        }
    }

    // ---- ewise thread state (tid < 80): u = tid%40, b = tid/40 ------------
    const int ue = tid % 40;
    const int be = tid / 40;
    const int ug = rank * QH + ue;                 // global unit
    float bh_r = 0.f, bh_z = 0.f, bh_n = 0.f;
    float xr = 0.f, xz = 0.f, xn = 0.f;
    size_t tokb = 0;
    if (tid < 80) {
        bh_r = bhh[dir * 480 + 0 * 160 + ug];
        bh_z = bhh[dir * 480 + 1 * 160 + ug];
        bh_n = bhh[dir * 480 + 2 * 160 + ug];
        tokb = (size_t)(b0 + be) * T_SEQ;
        const int t0 = dir ? (T_SEQ - 1) : 0;
        const float* xp = xw + (tokb + t0) * 960 + dir * 480 + ug;
        xr = xp[0]; xz = xp[160]; xn = xp[320];
    }

    for (int f = tid; f < 2 * NB * QH; f += blockDim.x)
        (&h_s[0][0][0])[f] = 0.f;
    __syncthreads();
    asm volatile("barrier.cluster.arrive.aligned;" ::: "memory");
    asm volatile("barrier.cluster.wait.aligned;" ::: "memory");

    int cur = 0;
    for (int s = 0; s < T_SEQ; s++) {
        const int t = dir ? (T_SEQ - 1 - s) : s;
        const int buf = s & 1;

        if (tid < 240) {
            ull a00 = 0ull, a01 = 0ull, a10 = 0ull, a11 = 0ull;
            const ulonglong2* H0 = reinterpret_cast<const ulonglong2*>(&h_s[cur][0][0]);
            const ulonglong2* H1 = reinterpret_cast<const ulonglong2*>(&h_s[cur][1][0]);
#pragma unroll
            for (int q = 0; q < 10; q++) {
                ulonglong2 hb0 = H0[q];     // broadcast LDS.128
                ulonglong2 hb1 = H1[q];
                fma2(a00, wp0[2 * q],     hb0.x);
                fma2(a00, wp0[2 * q + 1], hb0.y);
                fma2(a01, wp0[2 * q],     hb1.x);
                fma2(a01, wp0[2 * q + 1], hb1.y);
                fma2(a10, wp1[2 * q],     hb0.x);
                fma2(a10, wp1[2 * q + 1], hb0.y);
                fma2(a11, wp1[2 * q],     hb1.x);
                fma2(a11, wp1[2 * q + 1], hb1.y);
            }
            ull v0 = pk2(hsum2(a00), hsum2(a01));   // row0: (batch0, batch1)
            ull v1 = pk2(hsum2(a10), hsum2(a11));   // row1
            asm volatile("st.shared::cluster.b64 [%0], %1;" :: "r"(dst0[buf]), "l"(v0) : "memory");
            asm volatile("st.shared::cluster.b64 [%0], %1;" :: "r"(dst1[buf]), "l"(v1) : "memory");
        }
        asm volatile("barrier.cluster.arrive.aligned;" ::: "memory");
        asm volatile("barrier.cluster.wait.aligned;" ::: "memory");

        if (tid < 80) {
            float sr = 0.f, sz = 0.f, sn = 0.f;
#pragma unroll
            for (int sd = 0; sd < 4; sd++) {
                sr += a_part[buf][sd][0][ue][be];
                sz += a_part[buf][sd][1][ue][be];
                sn += a_part[buf][sd][2][ue][be];
            }
            float r = 1.f / (1.f + expf(-(xr + sr + bh_r)));
            float z = 1.f / (1.f + expf(-(xz + sz + bh_z)));
            float n = tanhf(xn + r * (sn + bh_n));
            float hp = h_s[cur][be][ue];
            float hnew = (1.f - z) * n + z * hp;
            h_s[cur ^ 1][be][ue] = hnew;
            out[(tokb + t) * 320 + dir * 160 + ug] = hnew;

            // prefetch next step's xW (hidden behind next matvec + barrier)
            if (s + 1 < T_SEQ) {
                const int tn = dir ? (T_SEQ - 2 - s) : (s + 1);
                const float* xp = xw + (tokb + tn) * 960 + dir * 480 + ug;
                xr = xp[0]; xz = xp[160]; xn = xp[320];
            }
        }
        __syncthreads();
        cur ^= 1;
    }

    // no CTA exits while peers may still target its SMEM
    asm volatile("barrier.cluster.arrive.aligned;" ::: "memory");
    asm volatile("barrier.cluster.wait.aligned;" ::: "memory");
}

// ------------------------------ attention bits -----------------------------
__global__ void __launch_bounds__(256) logits_kernel(
    const float* __restrict__ keys, const float* __restrict__ sw,
    const float* __restrict__ sb, float* __restrict__ logits)
{
    int warp = (blockIdx.x * blockDim.x + threadIdx.x) >> 5;
    int lane = threadIdx.x & 31;
    if (warp >= NTOK) return;
    const float* kr = keys + (size_t)warp * 160;
    float a0 = 0.f, a1 = 0.f, a2 = 0.f, a3 = 0.f;
    for (int k = lane; k < 160; k += 32) {
        float kv = kr[k];
        a0 = fmaf(kv, sw[0 * 160 + k], a0);
        a1 = fmaf(kv, sw[1 * 160 + k], a1);
        a2 = fmaf(kv, sw[2 * 160 + k], a2);
        a3 = fmaf(kv, sw[3 * 160 + k], a3);
    }
#pragma unroll
    for (int off = 16; off; off >>= 1) {
        a0 += __shfl_xor_sync(0xffffffffu, a0, off);
        a1 += __shfl_xor_sync(0xffffffffu, a1, off);
        a2 += __shfl_xor_sync(0xffffffffu, a2, off);
        a3 += __shfl_xor_sync(0xffffffffu, a3, off);
    }
    if (lane == 0) {
        float* o = logits + (size_t)warp * 4;
        o[0] = a0 + sb[0]; o[1] = a1 + sb[1]; o[2] = a2 + sb[2]; o[3] = a3 + sb[3];
    }
}

__global__ void __launch_bounds__(512) motion_kernel(
    const float* __restrict__ x, float* __restrict__ motion)
{
    __shared__ float sd[512];
    __shared__ float red[512];
    int b = blockIdx.x, t = threadIdx.x;
    float d = 0.f;
    if (t >= 1) {
        const float4* r1 = reinterpret_cast<const float4*>(x + ((size_t)b * 512 + t) * 128);
        const float4* r0 = reinterpret_cast<const float4*>(x + ((size_t)b * 512 + t - 1) * 128);
        float acc = 0.f;
#pragma unroll 8
        for (int q = 0; q < 32; q++) {
            float4 a = r1[q], c = r0[q];
            float dx = a.x - c.x, dy = a.y - c.y, dz = a.z - c.z, dw = a.w - c.w;
            acc += dx * dx + dy * dy + dz * dz + dw * dw;
        }
        d = sqrtf(acc);
    }
    sd[t] = d;
    __syncthreads();
    if (t == 0) sd[0] = sd[1];
    __syncthreads();
    d = sd[t];
    red[t] = d; __syncthreads();
    for (int off = 256; off; off >>= 1) { if (t < off) red[t] += red[t + off]; __syncthreads(); }
    float mean = red[0] / 512.f;
    __syncthreads();
    float dd = d - mean;
    red[t] = dd * dd; __syncthreads();
    for (int off = 256; off; off >>= 1) { if (t < off) red[t] += red[t + off]; __syncthreads(); }
    float stdv = sqrtf(red[0] / 511.f);
    motion[(size_t)b * 512 + t] = (d - mean) / (stdv + 1e-6f);
}

__global__ void __launch_bounds__(512) softmax_kernel(
    const float* __restrict__ logits, const float* __restrict__ motion,
    float* __restrict__ wmean_out)
{
    __shared__ float4 red[512];
    int b = blockIdx.x, t = threadIdx.x;
    size_t tok = (size_t)b * 512 + t;
    float4 l = *reinterpret_cast<const float4*>(logits + tok * 4);
    float m = motion[tok];
    l.x += m; l.y += m; l.z += m; l.w += m;
    red[t] = l; __syncthreads();
    for (int off = 256; off; off >>= 1) {
        if (t < off) {
            float4 a = red[t], c = red[t + off];
            a.x = fmaxf(a.x, c.x); a.y = fmaxf(a.y, c.y);
            a.z = fmaxf(a.z, c.z); a.w = fmaxf(a.w, c.w);
            red[t] = a;
        }
        __syncthreads();
    }
    float4 mx = red[0];
    __syncthreads();
    float4 e;
    e.x = expf(l.x - mx.x); e.y = expf(l.y - mx.y);
    e.z = expf(l.z - mx.z); e.w = expf(l.w - mx.w);
    red[t] = e; __syncthreads();
    for (int off = 256; off; off >>= 1) {
        if (t < off) {
            float4 a = red[t], c = red[t + off];
            a.x += c.x; a.y += c.y; a.z += c.z; a.w += c.w;
            red[t] = a;
        }
        __syncthreads();
    }
    float4 s = red[0];
    wmean_out[tok] = 0.25f * (e.x / s.x + e.y / s.y + e.z / s.z + e.w / s.w);
}

__global__ void __launch_bounds__(320) pool_kernel(
    const float* __restrict__ seq, const float* __restrict__ wm,
    float* __restrict__ pooled)
{
    __shared__ float sw[512];
    int b = blockIdx.x, d = threadIdx.x;
    for (int i = d; i < 512; i += 320) sw[i] = wm[(size_t)b * 512 + i];
    __syncthreads();
    float acc = 0.f;
    const float* sp = seq + (size_t)b * 512 * 320 + d;
    for (int t = 0; t < 512; t++) acc = fmaf(sp[(size_t)t * 320], sw[t], acc);
    pooled[b * 320 + d] = acc;
}

__global__ void __launch_bounds__(256) final_kernel(
    const float* __restrict__ pooled, const float* __restrict__ pw,
    const float* __restrict__ pb, const float* __restrict__ lng,
    const float* __restrict__ lnb, float* __restrict__ out)
{
    __shared__ float sp[320];
    __shared__ float red[256];
    int b = blockIdx.x, e = threadIdx.x;
    for (int i = e; i < 320; i += 256) sp[i] = pooled[b * 320 + i];
    __syncthreads();
    float acc = 0.f;
    const float* wr = pw + (size_t)e * 320;
#pragma unroll 4
    for (int k = 0; k < 320; k += 4) {
        acc = fmaf(wr[k + 0], sp[k + 0], acc);
        acc = fmaf(wr[k + 1], sp[k + 1], acc);
        acc = fmaf(wr[k + 2], sp[k + 2], acc);
        acc = fmaf(wr[k + 3], sp[k + 3], acc);
    }
    acc += pb[e];
    red[e] = acc; __syncthreads();
    for (int off = 128; off; off >>= 1) { if (e < off) red[e] += red[e + off]; __syncthreads(); }
    float mean = red[0] / 256.f;
    __syncthreads();
    float dd = acc - mean;
    red[e] = dd * dd; __syncthreads();
    for (int off = 128; off; off >>= 1) { if (e < off) red[e] += red[e + off]; __syncthreads(); }
    float var = red[0] / 256.f;
    __syncthreads();
    float v = dd * rsqrtf(var + 1e-5f) * lng[e] + lnb[e];
    red[e] = v * v; __syncthreads();
    for (int off = 128; off; off >>= 1) { if (e < off) red[e] += red[e + off]; __syncthreads(); }
    float nrm = fmaxf(sqrtf(red[0]), 1e-12f);
    out[b * 256 + e] = v / nrm;
}

// ------------------------------- launch -------------------------------------
extern "C" void kernel_launch(void* const* d_in, const int* in_sizes, int n_in,
                              void* d_out, int out_size)
{
    const float* x       = (const float*)d_in[0];
    const float* Wih0    = (const float*)d_in[1];
    const float* Whh0    = (const float*)d_in[2];
    const float* bih0    = (const float*)d_in[3];
    const float* bhh0    = (const float*)d_in[4];
    const float* Wih1    = (const float*)d_in[5];
    const float* Whh1    = (const float*)d_in[6];
    const float* bih1    = (const float*)d_in[7];
    const float* bhh1    = (const float*)d_in[8];
    const float* key_w   = (const float*)d_in[9];
    const float* key_b   = (const float*)d_in[10];
    const float* score_w = (const float*)d_in[11];
    const float* score_b = (const float*)d_in[12];
    const float* proj_w  = (const float*)d_in[13];
    const float* proj_b  = (const float*)d_in[14];
    const float* ln_g    = (const float*)d_in[15];
    const float* ln_b    = (const float*)d_in[16];
    float* out = (float*)d_out;
    float* out_emb = out;            // (64, 256)
    float* out_wm  = out + 64 * 256; // (64, 512)

    float *xw, *h1, *seq, *keys, *logits, *motion, *pooled;
    cudaGetSymbolAddress((void**)&xw,     g_xw);
    cudaGetSymbolAddress((void**)&h1,     g_h1);
    cudaGetSymbolAddress((void**)&seq,    g_seq);
    cudaGetSymbolAddress((void**)&keys,   g_keys);
    cudaGetSymbolAddress((void**)&logits, g_logits);
    cudaGetSymbolAddress((void**)&motion, g_motion);
    cudaGetSymbolAddress((void**)&pooled, g_pooled);

    // motion is independent of the GRU chain
    motion_kernel<<<BATCH, 512>>>(x, motion);

    // layer 0
    sgemm_bias<<<dim3((960 + BN - 1) / BN, NTOK / BM), 256>>>(x, Wih0, bih0, xw, NTOK, 960, 128, 0);
    gru_layer<<<256, 256>>>(xw, Whh0, bhh0, h1);

    // layer 1
    sgemm_bias<<<dim3((960 + BN - 1) / BN, NTOK / BM), 256>>>(h1, Wih1, bih1, xw, NTOK, 960, 320, 0);
    gru_layer<<<256, 256>>>(xw, Whh1, bhh1, seq);

    // keys = tanh(seq @ key_w^T + key_b)
    sgemm_bias<<<dim3((160 + BN - 1) / BN, NTOK / BM), 256>>>(seq, key_w, key_b, keys, NTOK, 160, 320, 1);

    // attention logits, softmax over T (writes weights.mean to out_wm)
    logits_kernel<<<NTOK / 8, 256>>>(keys, score_w, score_b, logits);
    softmax_kernel<<<BATCH, 512>>>(logits, motion, out_wm);

    // pooled + projection + LN + L2 norm
    pool_kernel<<<BATCH, 320>>>(seq, out_wm, pooled);
    final_kernel<<<BATCH, 256>>>(pooled, proj_w, proj_b, ln_g, ln_b, out_emb);
}